// round 14
// baseline (speedup 1.0000x reference)
#include <cuda_runtime.h>
#include <cuda_fp16.h>
#include <cstdint>

// Problem constants
#define NEXP   8
#define DDIM   1024
#define IDIM   2048
#define KTOP   2
#define NTOK   4096               // B*S
#define NASN   (NTOK * KTOP)      // 8192 assignments

// ---------------- device scratch (no allocations allowed) ----------------
__device__ int    g_is64;
__device__ int    g_count[NEXP];
__device__ int    g_offset[NEXP];
__device__ int    g_tok[NASN];
__device__ int    g_pos[NASN];                          // assignment i -> sorted position
__device__ float  g_wt[NASN];
__device__ __half g_xh[(size_t)NTOK * DDIM];            // 8 MB  x (fp16)
__device__ __half g_h[(size_t)NASN * IDIM];             // 32 MB silu(h) (fp16)
__device__ __half g_w1h[(size_t)NEXP * DDIM * IDIM];    // 32 MB w1 (fp16)
__device__ __half g_w2h[(size_t)NEXP * DDIM * IDIM];    // 32 MB w2 (fp16)
__device__ float  g_o[(size_t)NASN * DDIM];             // 64 MB weighted partials

// ---------------- helpers ----------------
__device__ __forceinline__ uint32_t h2_bits(__half2 h) {
    return *(uint32_t*)&h;
}

__device__ __forceinline__ uint32_t smem_u32(const void* p) {
    uint32_t a;
    asm("{ .reg .u64 t; cvta.to.shared.u64 t, %1; cvt.u32.u64 %0, t; }" : "=r"(a) : "l"(p));
    return a;
}

__device__ __forceinline__ void cp_async16(uint32_t dst, const void* src, uint32_t src_bytes) {
    asm volatile("cp.async.cg.shared.global [%0], [%1], 16, %2;\n"
                 :: "r"(dst), "l"(src), "r"(src_bytes) : "memory");
}
__device__ __forceinline__ void cp_commit() {
    asm volatile("cp.async.commit_group;" ::: "memory");
}
__device__ __forceinline__ void cp_wait1() {
    asm volatile("cp.async.wait_group 1;" ::: "memory");
}

__device__ __forceinline__ void ldsm_x4(uint32_t& r0, uint32_t& r1, uint32_t& r2, uint32_t& r3,
                                        uint32_t addr) {
    asm volatile("ldmatrix.sync.aligned.m8n8.x4.shared.b16 {%0,%1,%2,%3}, [%4];"
                 : "=r"(r0), "=r"(r1), "=r"(r2), "=r"(r3) : "r"(addr));
}

__device__ __forceinline__ void ldsm_x4_t(uint32_t& r0, uint32_t& r1, uint32_t& r2, uint32_t& r3,
                                          uint32_t addr) {
    asm volatile("ldmatrix.sync.aligned.m8n8.x4.trans.shared.b16 {%0,%1,%2,%3}, [%4];"
                 : "=r"(r0), "=r"(r1), "=r"(r2), "=r"(r3) : "r"(addr));
}

__device__ __forceinline__ void mma_f16_k16(float* c, const uint32_t* a, uint32_t b0, uint32_t b1) {
    asm volatile(
        "mma.sync.aligned.m16n8k16.row.col.f32.f16.f16.f32 "
        "{%0,%1,%2,%3}, {%4,%5,%6,%7}, {%8,%9}, {%0,%1,%2,%3};\n"
        : "+f"(c[0]), "+f"(c[1]), "+f"(c[2]), "+f"(c[3])
        : "r"(a[0]), "r"(a[1]), "r"(a[2]), "r"(a[3]), "r"(b0), "r"(b1));
}

// Fetch expert id for assignment i, handling int32 vs int64 wire format.
__device__ __forceinline__ int get_expert(const int* se32, int i) {
    int v = g_is64 ? se32[2 * i] : se32[i];   // little-endian low word for int64
    return v & (NEXP - 1);
}

// ---------------- prep: convert x + dtype detection ----------------
__global__ void prep_kernel(const float4* __restrict__ x, const int* __restrict__ se32, int n4) {
    int i = blockIdx.x * blockDim.x + threadIdx.x;
    if (blockIdx.x == 0 && threadIdx.x == 0) {
        int nz = 0;
        #pragma unroll 8
        for (int j = 1; j < 256; j += 2) nz |= se32[j];
        g_is64 = (nz == 0) ? 1 : 0;
    }
    if (i < n4) {
        float4 v = x[i];
        uint2 u;
        u.x = h2_bits(__floats2half2_rn(v.x, v.y));
        u.y = h2_bits(__floats2half2_rn(v.z, v.w));
        ((uint2*)g_xh)[i] = u;
    }
}

// ---------------- f32 -> f16 conversion pass for weights ----------------
__global__ void conv_half_kernel(const float4* __restrict__ in, uint2* __restrict__ outp, int n4) {
    int i = blockIdx.x * blockDim.x + threadIdx.x;
    if (i < n4) {
        float4 v = in[i];
        uint2 u;
        u.x = h2_bits(__floats2half2_rn(v.x, v.y));
        u.y = h2_bits(__floats2half2_rn(v.z, v.w));
        outp[i] = u;
    }
}

// ---------------- routing: warp-per-expert ballot scan (deterministic, stable) ----------------
__global__ void route_kernel(const int* __restrict__ se32, const float* __restrict__ rw) {
    const int tid  = threadIdx.x;
    const int warp = tid >> 5;          // warp w owns expert w
    const int lane = tid & 31;
    const unsigned lt = (1u << lane) - 1u;

    int cnt = 0;
    for (int it = 0; it < NASN / 32; it++) {
        int i = it * 32 + lane;
        unsigned m = __ballot_sync(0xFFFFFFFFu, get_expert(se32, i) == warp);
        cnt += __popc(m);
    }
    if (lane == 0) g_count[warp] = cnt;
    __syncthreads();
    if (tid == 0) {
        int off = 0;
        for (int e = 0; e < NEXP; e++) { g_offset[e] = off; off += g_count[e]; }
    }
    __syncthreads();

    int base = g_offset[warp];
    for (int it = 0; it < NASN / 32; it++) {
        int i = it * 32 + lane;
        bool mine = (get_expert(se32, i) == warp);
        unsigned m = __ballot_sync(0xFFFFFFFFu, mine);
        if (mine) {
            int r = __popc(m & lt);
            g_tok[base + r] = i / KTOP;
            g_wt[base + r]  = rw[i];
            g_pos[i]        = base + r;
        }
        base += __popc(m);
    }
}

// ---------------- final reduce: out[t] = g_o[pos(2t)] + g_o[pos(2t+1)] ----------------
__global__ void reduce_kernel(float4* __restrict__ out, int n4) {
    int i = blockIdx.x * blockDim.x + threadIdx.x;
    if (i < n4) {
        int t  = i >> 8;            // DDIM/4 = 256 float4 per token
        int c4 = i & 255;
        int p0 = g_pos[2 * t];
        int p1 = g_pos[2 * t + 1];
        float4 a = ((const float4*)g_o)[(size_t)p0 * 256 + c4];
        float4 b = ((const float4*)g_o)[(size_t)p1 * 256 + c4];
        out[i] = make_float4(a.x + b.x, a.y + b.y, a.z + b.z, a.w + b.w);
    }
}

// ---------------- grouped GEMM (fp16 mma m16n8k16 + ldmatrix, 128x128x32, cp.async 3-stage) ----------------
// SECOND == false : g_h = half(silu(gather(g_xh) @ g_w1h))
// SECOND == true  : g_o[row] = (g_h @ g_w2h) * wt   (plain STG, no atomics)
template <int KDIM, int NDIM, bool SECOND>
__global__ __launch_bounds__(256)
void moe_gemm() {
    constexpr int BM = 128, BN = 128, BK = 32;
    constexpr int ASTR = 40;    // halves per A row
    constexpr int BSTR = 136;   // halves per B row
    constexpr int NSTAGE = 3;
    constexpr int A_HALVES = BM * ASTR;                  // 5120
    constexpr int STAGE_H  = A_HALVES + BK * BSTR;       // 9472 halves = 18944 B
    constexpr int NKB      = KDIM / BK;

    extern __shared__ __half sh[];
    const uint32_t sb = smem_u32(sh);

    const __half* Ain  = SECOND ? g_h : g_xh;
    const __half* Wall = SECOND ? g_w2h : g_w1h;

    const int e   = blockIdx.z;
    const int cnt = g_count[e];
    if ((int)blockIdx.y * BM >= cnt) return;

    const int off     = g_offset[e];
    const int rowBase = off + blockIdx.y * BM;
    const int rowEnd  = off + cnt;
    const int nBase   = blockIdx.x * BN;
    const __half* Wp  = Wall + (size_t)e * KDIM * NDIM;

    const int tid  = threadIdx.x;
    const int lane = tid & 31;
    const int warp = tid >> 5;
    const int gq   = lane >> 2;          // groupID 0..7
    const int tig  = lane & 3;           // thread-in-group 0..3
    const int wm   = (warp >> 1) * 32;   // 4 warp-rows of 32
    const int wn   = (warp & 1) * 64;    // 2 warp-cols of 64

    // ldmatrix per-lane addressing
    const int lg = lane >> 3;
    const int lr = lane & 7;
    const int mrow_off = ((lg & 1) ? 8 : 0) + lr;
    const int kcol_off = (lg >= 2) ? 8 : 0;

    // ---- copy plans (uint4 = 8 halves, cp.async 16B) ----
    const __half* asrc[2]; uint32_t adst[2]; uint32_t abytes[2];
    #pragma unroll
    for (int j = 0; j < 2; j++) {
        int chunk = tid + j * 256;
        int r = chunk >> 2, c8 = (chunk & 3) * 8;
        adst[j] = (uint32_t)(r * ASTR + c8) * 2u;
        int grow = rowBase + r;
        bool v = (grow < rowEnd);
        abytes[j] = v ? 16u : 0u;
        asrc[j] = v ? (Ain + (size_t)(SECOND ? grow : g_tok[grow]) * KDIM + c8) : Ain;
    }
    const __half* bsrc[2]; uint32_t bdst[2];
    #pragma unroll
    for (int j = 0; j < 2; j++) {
        int chunk = tid + j * 256;
        int k = chunk >> 4, c8 = (chunk & 15) * 8;
        bdst[j] = (uint32_t)(A_HALVES + k * BSTR + c8) * 2u;
        bsrc[j] = Wp + (size_t)k * NDIM + nBase + c8;
    }

    auto load_stage = [&](int s, int kb) {
        const uint32_t sbase = sb + (uint32_t)s * (STAGE_H * 2);
        const int koff = kb * BK;
        #pragma unroll
        for (int j = 0; j < 2; j++) cp_async16(sbase + adst[j], asrc[j] + koff, abytes[j]);
        #pragma unroll
        for (int j = 0; j < 2; j++) cp_async16(sbase + bdst[j], bsrc[j] + (size_t)koff * NDIM, 16u);
    };

    float acc[2][8][4];
    #pragma unroll
    for (int mt = 0; mt < 2; mt++)
        #pragma unroll
        for (int nt = 0; nt < 8; nt++)
            #pragma unroll
            for (int q = 0; q < 4; q++) acc[mt][nt][q] = 0.f;

    auto compute = [&](int s) {
        const uint32_t abase = sb + (uint32_t)s * (STAGE_H * 2);
        const uint32_t bbase = abase + (uint32_t)(A_HALVES * 2);
        #pragma unroll
        for (int ks = 0; ks < 2; ks++) {
            const int k0 = ks * 16;
            uint32_t a[2][4];
            #pragma unroll
            for (int mt = 0; mt < 2; mt++) {
                uint32_t addr = abase +
                    (uint32_t)((wm + mt * 16 + mrow_off) * ASTR + k0 + kcol_off) * 2u;
                ldsm_x4(a[mt][0], a[mt][1], a[mt][2], a[mt][3], addr);
            }
            uint32_t b[4][4];
            #pragma unroll
            for (int nt2 = 0; nt2 < 4; nt2++) {
                uint32_t addr = bbase +
                    (uint32_t)((k0 + mrow_off) * BSTR + wn + nt2 * 16 + kcol_off) * 2u;
                ldsm_x4_t(b[nt2][0], b[nt2][1], b[nt2][2], b[nt2][3], addr);
            }
            #pragma unroll
            for (int nt2 = 0; nt2 < 4; nt2++) {
                mma_f16_k16(acc[0][2 * nt2],     a[0], b[nt2][0], b[nt2][1]);
                mma_f16_k16(acc[1][2 * nt2],     a[1], b[nt2][0], b[nt2][1]);
                mma_f16_k16(acc[0][2 * nt2 + 1], a[0], b[nt2][2], b[nt2][3]);
                mma_f16_k16(acc[1][2 * nt2 + 1], a[1], b[nt2][2], b[nt2][3]);
            }
        }
    };

    // prologue: stages for kb=0,1 in flight
    load_stage(0, 0); cp_commit();
    load_stage(1, 1); cp_commit();

    int s = 0;
    for (int kb = 0; kb < NKB; ++kb) {
        cp_wait1();
        __syncthreads();
        if (kb + 2 < NKB) load_stage((s + 2) % NSTAGE, kb + 2);
        cp_commit();
        compute(s);
        s = (s + 1) % NSTAGE;
    }

    // ---------------- epilogue ----------------
    #pragma unroll
    for (int mt = 0; mt < 2; mt++) {
        #pragma unroll
        for (int half = 0; half < 2; half++) {
            int rloc = wm + mt * 16 + gq + half * 8;
            int grow = rowBase + rloc;
            if (grow >= rowEnd) continue;
            if (SECOND) {
                const float wgt = g_wt[grow];
                float* orow = g_o + (size_t)grow * NDIM + nBase;
                #pragma unroll
                for (int nt = 0; nt < 8; nt++) {
                    int cc = wn + nt * 8 + tig * 2;
                    float2 v;
                    v.x = acc[mt][nt][half * 2 + 0] * wgt;
                    v.y = acc[mt][nt][half * 2 + 1] * wgt;
                    *(float2*)(orow + cc) = v;
                }
            } else {
                __half* hrow = g_h + (size_t)grow * NDIM + nBase;
                #pragma unroll
                for (int nt = 0; nt < 8; nt++) {
                    int cc = wn + nt * 8 + tig * 2;
                    float v0 = acc[mt][nt][half * 2 + 0];
                    float v1 = acc[mt][nt][half * 2 + 1];
                    float s0 = v0 / (1.f + __expf(-v0));   // silu
                    float s1 = v1 / (1.f + __expf(-v1));
                    *(__half2*)(hrow + cc) = __floats2half2_rn(s0, s1);
                }
            }
        }
    }
}

// ---------------- launch ----------------
extern "C" void kernel_launch(void* const* d_in, const int* in_sizes, int n_in,
                              void* d_out, int out_size) {
    const float* x    = (const float*)d_in[0];
    const float* rw   = (const float*)d_in[1];
    const int*   se32 = (const int*)d_in[2];
    const float* w1   = (const float*)d_in[3];
    const float* w2   = (const float*)d_in[4];
    float*       out  = (float*)d_out;

    constexpr int SMEM_BYTES = 3 * ((128 * 40 + 32 * 136) * 2);  // 56832

    static void* p_w1h = nullptr;
    static void* p_w2h = nullptr;
    if (!p_w1h) {
        cudaGetSymbolAddress(&p_w1h, g_w1h);
        cudaGetSymbolAddress(&p_w2h, g_w2h);
        cudaFuncSetAttribute((const void*)moe_gemm<DDIM, IDIM, false>,
                             cudaFuncAttributeMaxDynamicSharedMemorySize, SMEM_BYTES);
        cudaFuncSetAttribute((const void*)moe_gemm<IDIM, DDIM, true>,
                             cudaFuncAttributeMaxDynamicSharedMemorySize, SMEM_BYTES);
    }

    int n4 = out_size / 4;                 // 1M float4 (out and x same size)
    int w4 = (NEXP * DDIM * IDIM) / 4;     // 4M float4 per weight tensor

    // 1: prep (convert x + dtype), 2: route, 3-4: weight conversions
    prep_kernel<<<(n4 + 255) / 256, 256>>>((const float4*)x, se32, n4);
    route_kernel<<<1, 256>>>(se32, rw);
    conv_half_kernel<<<(w4 + 255) / 256, 256>>>((const float4*)w1, (uint2*)p_w1h, w4);
    conv_half_kernel<<<(w4 + 255) / 256, 256>>>((const float4*)w2, (uint2*)p_w2h, w4);

    // 5: GEMM1
    dim3 g1(IDIM / 128, NASN / 128, NEXP);   // (16, 64, 8)
    moe_gemm<DDIM, IDIM, false><<<g1, 256, SMEM_BYTES>>>();

    // 6: GEMM2 (ncu -s 5 -c 1 captures this)
    dim3 g2(DDIM / 128, NASN / 128, NEXP);   // (8, 64, 8)
    moe_gemm<IDIM, DDIM, true><<<g2, 256, SMEM_BYTES>>>();

    // 7: reduce partials into output
    reduce_kernel<<<(n4 + 255) / 256, 256>>>((float4*)out, n4);
}

// round 15
// speedup vs baseline: 1.0346x; 1.0346x over previous
#include <cuda_runtime.h>
#include <cuda_fp16.h>
#include <cstdint>

// Problem constants
#define NEXP   8
#define DDIM   1024
#define IDIM   2048
#define KTOP   2
#define NTOK   4096               // B*S
#define NASN   (NTOK * KTOP)      // 8192 assignments

// ---------------- device scratch (no allocations allowed) ----------------
__device__ int    g_is64;
__device__ int    g_count[NEXP];
__device__ int    g_offset[NEXP];
__device__ int    g_tok[NASN];
__device__ float  g_wt[NASN];
__device__ __half g_xh[(size_t)NTOK * DDIM];            // 8 MB  x (fp16)
__device__ __half g_h[(size_t)NASN * IDIM];             // 32 MB silu(h) (fp16)
__device__ __half g_w1h[(size_t)NEXP * DDIM * IDIM];    // 32 MB w1 (fp16)
__device__ __half g_w2h[(size_t)NEXP * DDIM * IDIM];    // 32 MB w2 (fp16)

// ---------------- helpers ----------------
__device__ __forceinline__ uint32_t h2_bits(__half2 h) {
    return *(uint32_t*)&h;
}

__device__ __forceinline__ uint32_t smem_u32(const void* p) {
    uint32_t a;
    asm("{ .reg .u64 t; cvta.to.shared.u64 t, %1; cvt.u32.u64 %0, t; }" : "=r"(a) : "l"(p));
    return a;
}

__device__ __forceinline__ void cp_async16(uint32_t dst, const void* src, uint32_t src_bytes) {
    asm volatile("cp.async.cg.shared.global [%0], [%1], 16, %2;\n"
                 :: "r"(dst), "l"(src), "r"(src_bytes) : "memory");
}
__device__ __forceinline__ void cp_commit() {
    asm volatile("cp.async.commit_group;" ::: "memory");
}
__device__ __forceinline__ void cp_wait1() {
    asm volatile("cp.async.wait_group 1;" ::: "memory");
}

__device__ __forceinline__ void ldsm_x4(uint32_t& r0, uint32_t& r1, uint32_t& r2, uint32_t& r3,
                                        uint32_t addr) {
    asm volatile("ldmatrix.sync.aligned.m8n8.x4.shared.b16 {%0,%1,%2,%3}, [%4];"
                 : "=r"(r0), "=r"(r1), "=r"(r2), "=r"(r3) : "r"(addr));
}

__device__ __forceinline__ void ldsm_x4_t(uint32_t& r0, uint32_t& r1, uint32_t& r2, uint32_t& r3,
                                          uint32_t addr) {
    asm volatile("ldmatrix.sync.aligned.m8n8.x4.trans.shared.b16 {%0,%1,%2,%3}, [%4];"
                 : "=r"(r0), "=r"(r1), "=r"(r2), "=r"(r3) : "r"(addr));
}

__device__ __forceinline__ void mma_f16_k16(float* c, const uint32_t* a, uint32_t b0, uint32_t b1) {
    asm volatile(
        "mma.sync.aligned.m16n8k16.row.col.f32.f16.f16.f32 "
        "{%0,%1,%2,%3}, {%4,%5,%6,%7}, {%8,%9}, {%0,%1,%2,%3};\n"
        : "+f"(c[0]), "+f"(c[1]), "+f"(c[2]), "+f"(c[3])
        : "r"(a[0]), "r"(a[1]), "r"(a[2]), "r"(a[3]), "r"(b0), "r"(b1));
}

// Fetch expert id for assignment i, handling int32 vs int64 wire format.
__device__ __forceinline__ int get_expert(const int* se32, int i) {
    int v = g_is64 ? se32[2 * i] : se32[i];   // little-endian low word for int64
    return v & (NEXP - 1);
}

// ---------------- prep: zero out + convert x + dtype detection (fused) ----------------
__global__ void prep_kernel(float4* __restrict__ out, const float4* __restrict__ x,
                            const int* __restrict__ se32, int n4) {
    int i = blockIdx.x * blockDim.x + threadIdx.x;
    if (blockIdx.x == 0 && threadIdx.x == 0) {
        int nz = 0;
        #pragma unroll 8
        for (int j = 1; j < 256; j += 2) nz |= se32[j];
        g_is64 = (nz == 0) ? 1 : 0;
    }
    if (i < n4) {
        out[i] = make_float4(0.f, 0.f, 0.f, 0.f);
        float4 v = x[i];
        uint2 u;
        u.x = h2_bits(__floats2half2_rn(v.x, v.y));
        u.y = h2_bits(__floats2half2_rn(v.z, v.w));
        ((uint2*)g_xh)[i] = u;
    }
}

// ---------------- f32 -> f16 conversion pass for weights ----------------
__global__ void conv_half_kernel(const float4* __restrict__ in, uint2* __restrict__ outp, int n4) {
    int i = blockIdx.x * blockDim.x + threadIdx.x;
    if (i < n4) {
        float4 v = in[i];
        uint2 u;
        u.x = h2_bits(__floats2half2_rn(v.x, v.y));
        u.y = h2_bits(__floats2half2_rn(v.z, v.w));
        outp[i] = u;
    }
}

// ---------------- routing: warp-per-expert ballot scan (deterministic, stable) ----------------
__global__ void route_kernel(const int* __restrict__ se32, const float* __restrict__ rw) {
    const int tid  = threadIdx.x;
    const int warp = tid >> 5;          // warp w owns expert w
    const int lane = tid & 31;
    const unsigned lt = (1u << lane) - 1u;

    int cnt = 0;
    for (int it = 0; it < NASN / 32; it++) {
        int i = it * 32 + lane;
        unsigned m = __ballot_sync(0xFFFFFFFFu, get_expert(se32, i) == warp);
        cnt += __popc(m);
    }
    if (lane == 0) g_count[warp] = cnt;
    __syncthreads();
    if (tid == 0) {
        int off = 0;
        for (int e = 0; e < NEXP; e++) { g_offset[e] = off; off += g_count[e]; }
    }
    __syncthreads();

    int base = g_offset[warp];
    for (int it = 0; it < NASN / 32; it++) {
        int i = it * 32 + lane;
        bool mine = (get_expert(se32, i) == warp);
        unsigned m = __ballot_sync(0xFFFFFFFFu, mine);
        if (mine) {
            int r = __popc(m & lt);
            g_tok[base + r] = i / KTOP;
            g_wt[base + r]  = rw[i];
        }
        base += __popc(m);
    }
}

// ---------------- grouped GEMM (fp16 mma m16n8k16 + ldmatrix, 128x128x32, cp.async 3-stage) ----------------
// SECOND == false : g_h = half(silu(gather(g_xh) @ g_w1h))
// SECOND == true  : out[tok] += (g_h @ g_w2h) * wt  (atomicAdd)
template <int KDIM, int NDIM, bool SECOND>
__global__ __launch_bounds__(256, 2)
void moe_gemm(float* __restrict__ Oglob) {
    constexpr int BM = 128, BN = 128, BK = 32;
    constexpr int ASTR = 40;    // halves per A row
    constexpr int BSTR = 136;   // halves per B row
    constexpr int NSTAGE = 3;
    constexpr int A_HALVES = BM * ASTR;                  // 5120
    constexpr int STAGE_H  = A_HALVES + BK * BSTR;       // 9472 halves = 18944 B
    constexpr int NKB      = KDIM / BK;

    extern __shared__ __half sh[];
    const uint32_t sb = smem_u32(sh);

    const __half* Ain  = SECOND ? g_h : g_xh;
    const __half* Wall = SECOND ? g_w2h : g_w1h;

    const int e   = blockIdx.z;
    const int cnt = g_count[e];
    if ((int)blockIdx.y * BM >= cnt) return;

    const int off     = g_offset[e];
    const int rowBase = off + blockIdx.y * BM;
    const int rowEnd  = off + cnt;
    const int nBase   = blockIdx.x * BN;
    const __half* Wp  = Wall + (size_t)e * KDIM * NDIM;

    const int tid  = threadIdx.x;
    const int lane = tid & 31;
    const int warp = tid >> 5;
    const int gq   = lane >> 2;          // groupID 0..7
    const int tig  = lane & 3;           // thread-in-group 0..3
    const int wm   = (warp >> 1) * 32;   // 4 warp-rows of 32
    const int wn   = (warp & 1) * 64;    // 2 warp-cols of 64

    // ldmatrix per-lane addressing
    const int lg = lane >> 3;
    const int lr = lane & 7;
    const int mrow_off = ((lg & 1) ? 8 : 0) + lr;
    const int kcol_off = (lg >= 2) ? 8 : 0;

    // ---- copy plans (uint4 = 8 halves, cp.async 16B) ----
    const __half* asrc[2]; uint32_t adst[2]; uint32_t abytes[2];
    #pragma unroll
    for (int j = 0; j < 2; j++) {
        int chunk = tid + j * 256;
        int r = chunk >> 2, c8 = (chunk & 3) * 8;
        adst[j] = (uint32_t)(r * ASTR + c8) * 2u;
        int grow = rowBase + r;
        bool v = (grow < rowEnd);
        abytes[j] = v ? 16u : 0u;
        asrc[j] = v ? (Ain + (size_t)(SECOND ? grow : g_tok[grow]) * KDIM + c8) : Ain;
    }
    const __half* bsrc[2]; uint32_t bdst[2];
    #pragma unroll
    for (int j = 0; j < 2; j++) {
        int chunk = tid + j * 256;
        int k = chunk >> 4, c8 = (chunk & 15) * 8;
        bdst[j] = (uint32_t)(A_HALVES + k * BSTR + c8) * 2u;
        bsrc[j] = Wp + (size_t)k * NDIM + nBase + c8;
    }

    auto load_stage = [&](int s, int kb) {
        const uint32_t sbase = sb + (uint32_t)s * (STAGE_H * 2);
        const int koff = kb * BK;
        #pragma unroll
        for (int j = 0; j < 2; j++) cp_async16(sbase + adst[j], asrc[j] + koff, abytes[j]);
        #pragma unroll
        for (int j = 0; j < 2; j++) cp_async16(sbase + bdst[j], bsrc[j] + (size_t)koff * NDIM, 16u);
    };

    float acc[2][8][4];
    #pragma unroll
    for (int mt = 0; mt < 2; mt++)
        #pragma unroll
        for (int nt = 0; nt < 8; nt++)
            #pragma unroll
            for (int q = 0; q < 4; q++) acc[mt][nt][q] = 0.f;

    auto compute = [&](int s) {
        const uint32_t abase = sb + (uint32_t)s * (STAGE_H * 2);
        const uint32_t bbase = abase + (uint32_t)(A_HALVES * 2);
        #pragma unroll
        for (int ks = 0; ks < 2; ks++) {
            const int k0 = ks * 16;
            uint32_t a[2][4];
            #pragma unroll
            for (int mt = 0; mt < 2; mt++) {
                uint32_t addr = abase +
                    (uint32_t)((wm + mt * 16 + mrow_off) * ASTR + k0 + kcol_off) * 2u;
                ldsm_x4(a[mt][0], a[mt][1], a[mt][2], a[mt][3], addr);
            }
            uint32_t b[4][4];
            #pragma unroll
            for (int nt2 = 0; nt2 < 4; nt2++) {
                uint32_t addr = bbase +
                    (uint32_t)((k0 + mrow_off) * BSTR + wn + nt2 * 16 + kcol_off) * 2u;
                ldsm_x4_t(b[nt2][0], b[nt2][1], b[nt2][2], b[nt2][3], addr);
            }
            #pragma unroll
            for (int nt2 = 0; nt2 < 4; nt2++) {
                mma_f16_k16(acc[0][2 * nt2],     a[0], b[nt2][0], b[nt2][1]);
                mma_f16_k16(acc[1][2 * nt2],     a[1], b[nt2][0], b[nt2][1]);
                mma_f16_k16(acc[0][2 * nt2 + 1], a[0], b[nt2][2], b[nt2][3]);
                mma_f16_k16(acc[1][2 * nt2 + 1], a[1], b[nt2][2], b[nt2][3]);
            }
        }
    };

    // prologue: stages for kb=0,1 in flight
    load_stage(0, 0); cp_commit();
    load_stage(1, 1); cp_commit();

    int s = 0;
    for (int kb = 0; kb < NKB; ++kb) {
        cp_wait1();
        __syncthreads();
        if (kb + 2 < NKB) load_stage((s + 2) % NSTAGE, kb + 2);
        cp_commit();
        compute(s);
        s = (s + 1) % NSTAGE;
    }

    // ---------------- epilogue ----------------
    #pragma unroll
    for (int mt = 0; mt < 2; mt++) {
        #pragma unroll
        for (int half = 0; half < 2; half++) {
            int rloc = wm + mt * 16 + gq + half * 8;
            int grow = rowBase + rloc;
            if (grow >= rowEnd) continue;
            if (SECOND) {
                const int   tok = g_tok[grow];
                const float wgt = g_wt[grow];
                float* orow = Oglob + (size_t)tok * NDIM + nBase;
                #pragma unroll
                for (int nt = 0; nt < 8; nt++) {
                    int cc = wn + nt * 8 + tig * 2;
                    atomicAdd(&orow[cc],     acc[mt][nt][half * 2 + 0] * wgt);
                    atomicAdd(&orow[cc + 1], acc[mt][nt][half * 2 + 1] * wgt);
                }
            } else {
                __half* hrow = g_h + (size_t)grow * NDIM + nBase;
                #pragma unroll
                for (int nt = 0; nt < 8; nt++) {
                    int cc = wn + nt * 8 + tig * 2;
                    float v0 = acc[mt][nt][half * 2 + 0];
                    float v1 = acc[mt][nt][half * 2 + 1];
                    float s0 = v0 / (1.f + __expf(-v0));   // silu
                    float s1 = v1 / (1.f + __expf(-v1));
                    *(__half2*)(hrow + cc) = __floats2half2_rn(s0, s1);
                }
            }
        }
    }
}

// ---------------- launch ----------------
extern "C" void kernel_launch(void* const* d_in, const int* in_sizes, int n_in,
                              void* d_out, int out_size) {
    const float* x    = (const float*)d_in[0];
    const float* rw   = (const float*)d_in[1];
    const int*   se32 = (const int*)d_in[2];
    const float* w1   = (const float*)d_in[3];
    const float* w2   = (const float*)d_in[4];
    float*       out  = (float*)d_out;

    constexpr int SMEM_BYTES = 3 * ((128 * 40 + 32 * 136) * 2);  // 56832

    static void* p_w1h = nullptr;
    static void* p_w2h = nullptr;
    if (!p_w1h) {
        cudaGetSymbolAddress(&p_w1h, g_w1h);
        cudaGetSymbolAddress(&p_w2h, g_w2h);
        cudaFuncSetAttribute((const void*)moe_gemm<DDIM, IDIM, false>,
                             cudaFuncAttributeMaxDynamicSharedMemorySize, SMEM_BYTES);
        cudaFuncSetAttribute((const void*)moe_gemm<IDIM, DDIM, true>,
                             cudaFuncAttributeMaxDynamicSharedMemorySize, SMEM_BYTES);
    }

    int n4 = out_size / 4;                 // 1M float4 (out and x same size)
    int w4 = (NEXP * DDIM * IDIM) / 4;     // 4M float4 per weight tensor

    // 1: prep (zero out + convert x + dtype), 2: route, 3-4: weight conversions
    prep_kernel<<<(n4 + 255) / 256, 256>>>((float4*)out, (const float4*)x, se32, n4);
    route_kernel<<<1, 256>>>(se32, rw);
    conv_half_kernel<<<(w4 + 255) / 256, 256>>>((const float4*)w1, (uint2*)p_w1h, w4);
    conv_half_kernel<<<(w4 + 255) / 256, 256>>>((const float4*)w2, (uint2*)p_w2h, w4);

    // 5: GEMM1
    dim3 g1(IDIM / 128, NASN / 128, NEXP);   // (16, 64, 8)
    moe_gemm<DDIM, IDIM, false><<<g1, 256, SMEM_BYTES>>>(out);

    // 6: GEMM2 (ncu -s 5 -c 1 captures this)
    dim3 g2(DDIM / 128, NASN / 128, NEXP);   // (8, 64, 8)
    moe_gemm<IDIM, DDIM, true><<<g2, 256, SMEM_BYTES>>>(out);
}

// round 16
// speedup vs baseline: 1.1368x; 1.0988x over previous
#include <cuda_runtime.h>
#include <cuda_fp16.h>
#include <cstdint>

// Problem constants
#define NEXP   8
#define DDIM   1024
#define IDIM   2048
#define KTOP   2
#define NTOK   4096               // B*S
#define NASN   (NTOK * KTOP)      // 8192 assignments

// ---------------- device scratch (no allocations allowed) ----------------
__device__ int    g_is64;
__device__ int    g_count[NEXP];
__device__ int    g_offset[NEXP];
__device__ int    g_tok[NASN];
__device__ float  g_wt[NASN];
__device__ __half g_xh[(size_t)NTOK * DDIM];            // 8 MB  x (fp16)
__device__ __half g_h[(size_t)NASN * IDIM];             // 32 MB silu(h) (fp16)
__device__ __half g_w1h[(size_t)NEXP * DDIM * IDIM];    // 32 MB w1 (fp16)
__device__ __half g_w2h[(size_t)NEXP * DDIM * IDIM];    // 32 MB w2 (fp16)

// ---------------- helpers ----------------
__device__ __forceinline__ uint32_t h2_bits(__half2 h) {
    return *(uint32_t*)&h;
}

__device__ __forceinline__ uint32_t smem_u32(const void* p) {
    uint32_t a;
    asm("{ .reg .u64 t; cvta.to.shared.u64 t, %1; cvt.u32.u64 %0, t; }" : "=r"(a) : "l"(p));
    return a;
}

__device__ __forceinline__ void cp_async16(uint32_t dst, const void* src, uint32_t src_bytes) {
    asm volatile("cp.async.cg.shared.global [%0], [%1], 16, %2;\n"
                 :: "r"(dst), "l"(src), "r"(src_bytes) : "memory");
}
__device__ __forceinline__ void cp_commit() {
    asm volatile("cp.async.commit_group;" ::: "memory");
}
__device__ __forceinline__ void cp_wait1() {
    asm volatile("cp.async.wait_group 1;" ::: "memory");
}

__device__ __forceinline__ void ldsm_x4(uint32_t& r0, uint32_t& r1, uint32_t& r2, uint32_t& r3,
                                        uint32_t addr) {
    asm volatile("ldmatrix.sync.aligned.m8n8.x4.shared.b16 {%0,%1,%2,%3}, [%4];"
                 : "=r"(r0), "=r"(r1), "=r"(r2), "=r"(r3) : "r"(addr));
}

__device__ __forceinline__ void ldsm_x4_t(uint32_t& r0, uint32_t& r1, uint32_t& r2, uint32_t& r3,
                                          uint32_t addr) {
    asm volatile("ldmatrix.sync.aligned.m8n8.x4.trans.shared.b16 {%0,%1,%2,%3}, [%4];"
                 : "=r"(r0), "=r"(r1), "=r"(r2), "=r"(r3) : "r"(addr));
}

__device__ __forceinline__ void mma_f16_k16(float* c, const uint32_t* a, uint32_t b0, uint32_t b1) {
    asm volatile(
        "mma.sync.aligned.m16n8k16.row.col.f32.f16.f16.f32 "
        "{%0,%1,%2,%3}, {%4,%5,%6,%7}, {%8,%9}, {%0,%1,%2,%3};\n"
        : "+f"(c[0]), "+f"(c[1]), "+f"(c[2]), "+f"(c[3])
        : "r"(a[0]), "r"(a[1]), "r"(a[2]), "r"(a[3]), "r"(b0), "r"(b1));
}

// Fetch expert id for assignment i, handling int32 vs int64 wire format.
__device__ __forceinline__ int get_expert(const int* se32, int i) {
    int v = g_is64 ? se32[2 * i] : se32[i];   // little-endian low word for int64
    return v & (NEXP - 1);
}

// ---------------- prep: zero out + convert x + dtype detection (fused) ----------------
__global__ void prep_kernel(float4* __restrict__ out, const float4* __restrict__ x,
                            const int* __restrict__ se32, int n4) {
    int i = blockIdx.x * blockDim.x + threadIdx.x;
    if (blockIdx.x == 0 && threadIdx.x == 0) {
        int nz = 0;
        #pragma unroll 8
        for (int j = 1; j < 256; j += 2) nz |= se32[j];
        g_is64 = (nz == 0) ? 1 : 0;
    }
    if (i < n4) {
        out[i] = make_float4(0.f, 0.f, 0.f, 0.f);
        float4 v = x[i];
        uint2 u;
        u.x = h2_bits(__floats2half2_rn(v.x, v.y));
        u.y = h2_bits(__floats2half2_rn(v.z, v.w));
        ((uint2*)g_xh)[i] = u;
    }
}

// ---------------- f32 -> f16 conversion pass for weights (w1 only; w2 fused into GEMM1) ----------------
__global__ void conv_half_kernel(const float4* __restrict__ in, uint2* __restrict__ outp, int n4) {
    int i = blockIdx.x * blockDim.x + threadIdx.x;
    if (i < n4) {
        float4 v = in[i];
        uint2 u;
        u.x = h2_bits(__floats2half2_rn(v.x, v.y));
        u.y = h2_bits(__floats2half2_rn(v.z, v.w));
        outp[i] = u;
    }
}

// ---------------- routing: warp-per-expert ballot scan (deterministic, stable) ----------------
__global__ void route_kernel(const int* __restrict__ se32, const float* __restrict__ rw) {
    const int tid  = threadIdx.x;
    const int warp = tid >> 5;          // warp w owns expert w
    const int lane = tid & 31;
    const unsigned lt = (1u << lane) - 1u;

    int cnt = 0;
    for (int it = 0; it < NASN / 32; it++) {
        int i = it * 32 + lane;
        unsigned m = __ballot_sync(0xFFFFFFFFu, get_expert(se32, i) == warp);
        cnt += __popc(m);
    }
    if (lane == 0) g_count[warp] = cnt;
    __syncthreads();
    if (tid == 0) {
        int off = 0;
        for (int e = 0; e < NEXP; e++) { g_offset[e] = off; off += g_count[e]; }
    }
    __syncthreads();

    int base = g_offset[warp];
    for (int it = 0; it < NASN / 32; it++) {
        int i = it * 32 + lane;
        bool mine = (get_expert(se32, i) == warp);
        unsigned m = __ballot_sync(0xFFFFFFFFu, mine);
        if (mine) {
            int r = __popc(m & lt);
            g_tok[base + r] = i / KTOP;
            g_wt[base + r]  = rw[i];
        }
        base += __popc(m);
    }
}

// ---------------- grouped GEMM (fp16 mma m16n8k16 + ldmatrix, 128x128x64, cp.async 3-stage) ----------------
// SECOND == false : g_h = half(silu(gather(g_xh) @ g_w1h)); blocks with z==NEXP convert w2 instead
// SECOND == true  : out[tok] += (g_h @ g_w2h) * wt  (atomicAdd)
template <int KDIM, int NDIM, bool SECOND>
__global__ __launch_bounds__(256, 2)
void moe_gemm(float* __restrict__ Oglob,
              const float4* __restrict__ cw_src, uint2* __restrict__ cw_dst) {
    constexpr int BM = 128, BN = 128, BK = 64;
    constexpr int ASTR = 72;    // halves per A row (144B stride -> distinct 16B slots mod 128)
    constexpr int BSTR = 136;   // halves per B row (272B stride, proven)
    constexpr int NSTAGE = 3;
    constexpr int A_HALVES = BM * ASTR;                  // 9216
    constexpr int STAGE_H  = A_HALVES + BK * BSTR;       // 17920 halves = 35840 B
    constexpr int NKB      = KDIM / BK;

    const int tid = threadIdx.x;

    // ---- fused w2 conversion blocks (GEMM1 grid only, z == NEXP) ----
    if (!SECOND && blockIdx.z == NEXP) {
        const int W4 = NEXP * DDIM * IDIM / 4;            // 4M float4
        int nblk = gridDim.x * gridDim.y;                 // 1024
        int bid  = blockIdx.y * gridDim.x + blockIdx.x;
        for (int i = bid * 256 + tid; i < W4; i += nblk * 256) {
            float4 v = cw_src[i];
            uint2 u;
            u.x = h2_bits(__floats2half2_rn(v.x, v.y));
            u.y = h2_bits(__floats2half2_rn(v.z, v.w));
            cw_dst[i] = u;
        }
        return;
    }

    extern __shared__ __half sh[];
    const uint32_t sb = smem_u32(sh);

    const __half* Ain  = SECOND ? g_h : g_xh;
    const __half* Wall = SECOND ? g_w2h : g_w1h;

    const int e   = blockIdx.z;
    const int cnt = g_count[e];
    if ((int)blockIdx.y * BM >= cnt) return;

    const int off     = g_offset[e];
    const int rowBase = off + blockIdx.y * BM;
    const int rowEnd  = off + cnt;
    const int nBase   = blockIdx.x * BN;
    const __half* Wp  = Wall + (size_t)e * KDIM * NDIM;

    const int lane = tid & 31;
    const int warp = tid >> 5;
    const int gq   = lane >> 2;          // groupID 0..7
    const int tig  = lane & 3;           // thread-in-group 0..3
    const int wm   = (warp >> 1) * 32;   // 4 warp-rows of 32
    const int wn   = (warp & 1) * 64;    // 2 warp-cols of 64

    // ldmatrix per-lane addressing
    const int lg = lane >> 3;
    const int lr = lane & 7;
    const int mrow_off = ((lg & 1) ? 8 : 0) + lr;
    const int kcol_off = (lg >= 2) ? 8 : 0;

    // ---- A row ids (only persistent copy-plan state; rest recomputed) ----
    int arowid[4];
    #pragma unroll
    for (int j = 0; j < 4; j++) {
        int chunk = tid + j * 256;
        int r = chunk >> 3;              // 0..127
        int grow = rowBase + r;
        arowid[j] = (grow < rowEnd) ? (SECOND ? grow : g_tok[grow]) : -1;
    }

    auto load_stage = [&](int st, int kb) {
        const uint32_t sbase = sb + (uint32_t)st * (STAGE_H * 2);
        const int koff = kb * BK;
        #pragma unroll
        for (int j = 0; j < 4; j++) {
            int chunk = tid + j * 256;
            int r  = chunk >> 3;
            int c8 = (chunk & 7) * 8;    // 0..56
            uint32_t dst = sbase + (uint32_t)(r * ASTR + c8) * 2u;
            const __half* src = (arowid[j] >= 0)
                ? (Ain + (size_t)arowid[j] * KDIM + koff + c8) : Ain;
            cp_async16(dst, src, (arowid[j] >= 0) ? 16u : 0u);
        }
        #pragma unroll
        for (int j = 0; j < 4; j++) {
            int chunk = tid + j * 256;
            int k  = chunk >> 4;         // 0..63
            int c8 = (chunk & 15) * 8;   // 0..120
            uint32_t dst = sbase + (uint32_t)(A_HALVES + k * BSTR + c8) * 2u;
            cp_async16(dst, Wp + (size_t)(koff + k) * NDIM + nBase + c8, 16u);
        }
    };

    float acc[2][8][4];
    #pragma unroll
    for (int mt = 0; mt < 2; mt++)
        #pragma unroll
        for (int nt = 0; nt < 8; nt++)
            #pragma unroll
            for (int q = 0; q < 4; q++) acc[mt][nt][q] = 0.f;

    auto compute = [&](int st) {
        const uint32_t abase = sb + (uint32_t)st * (STAGE_H * 2);
        const uint32_t bbase = abase + (uint32_t)(A_HALVES * 2);
        #pragma unroll
        for (int ks = 0; ks < BK / 16; ks++) {
            const int k0 = ks * 16;
            uint32_t a[2][4];
            #pragma unroll
            for (int mt = 0; mt < 2; mt++) {
                uint32_t addr = abase +
                    (uint32_t)((wm + mt * 16 + mrow_off) * ASTR + k0 + kcol_off) * 2u;
                ldsm_x4(a[mt][0], a[mt][1], a[mt][2], a[mt][3], addr);
            }
            uint32_t b[4][4];
            #pragma unroll
            for (int nt2 = 0; nt2 < 4; nt2++) {
                uint32_t addr = bbase +
                    (uint32_t)((k0 + mrow_off) * BSTR + wn + nt2 * 16 + kcol_off) * 2u;
                ldsm_x4_t(b[nt2][0], b[nt2][1], b[nt2][2], b[nt2][3], addr);
            }
            #pragma unroll
            for (int nt2 = 0; nt2 < 4; nt2++) {
                mma_f16_k16(acc[0][2 * nt2],     a[0], b[nt2][0], b[nt2][1]);
                mma_f16_k16(acc[1][2 * nt2],     a[1], b[nt2][0], b[nt2][1]);
                mma_f16_k16(acc[0][2 * nt2 + 1], a[0], b[nt2][2], b[nt2][3]);
                mma_f16_k16(acc[1][2 * nt2 + 1], a[1], b[nt2][2], b[nt2][3]);
            }
        }
    };

    // prologue: stages for kb=0,1 in flight
    load_stage(0, 0); cp_commit();
    load_stage(1, 1); cp_commit();

    int s = 0;
    for (int kb = 0; kb < NKB; ++kb) {
        cp_wait1();
        __syncthreads();
        if (kb + 2 < NKB) load_stage((s + 2) % NSTAGE, kb + 2);
        cp_commit();
        compute(s);
        s = (s + 1) % NSTAGE;
    }

    // ---------------- epilogue ----------------
    #pragma unroll
    for (int mt = 0; mt < 2; mt++) {
        #pragma unroll
        for (int half = 0; half < 2; half++) {
            int rloc = wm + mt * 16 + gq + half * 8;
            int grow = rowBase + rloc;
            if (grow >= rowEnd) continue;
            if (SECOND) {
                const int   tok = g_tok[grow];
                const float wgt = g_wt[grow];
                float* orow = Oglob + (size_t)tok * NDIM + nBase;
                #pragma unroll
                for (int nt = 0; nt < 8; nt++) {
                    int cc = wn + nt * 8 + tig * 2;
                    atomicAdd(&orow[cc],     acc[mt][nt][half * 2 + 0] * wgt);
                    atomicAdd(&orow[cc + 1], acc[mt][nt][half * 2 + 1] * wgt);
                }
            } else {
                __half* hrow = g_h + (size_t)grow * NDIM + nBase;
                #pragma unroll
                for (int nt = 0; nt < 8; nt++) {
                    int cc = wn + nt * 8 + tig * 2;
                    float v0 = acc[mt][nt][half * 2 + 0];
                    float v1 = acc[mt][nt][half * 2 + 1];
                    float s0 = v0 / (1.f + __expf(-v0));   // silu
                    float s1 = v1 / (1.f + __expf(-v1));
                    *(__half2*)(hrow + cc) = __floats2half2_rn(s0, s1);
                }
            }
        }
    }
}

// ---------------- launch ----------------
extern "C" void kernel_launch(void* const* d_in, const int* in_sizes, int n_in,
                              void* d_out, int out_size) {
    const float* x    = (const float*)d_in[0];
    const float* rw   = (const float*)d_in[1];
    const int*   se32 = (const int*)d_in[2];
    const float* w1   = (const float*)d_in[3];
    const float* w2   = (const float*)d_in[4];
    float*       out  = (float*)d_out;

    constexpr int SMEM_BYTES = 3 * ((128 * 72 + 64 * 136) * 2);  // 107520

    static void* p_w1h = nullptr;
    static void* p_w2h = nullptr;
    if (!p_w1h) {
        cudaGetSymbolAddress(&p_w1h, g_w1h);
        cudaGetSymbolAddress(&p_w2h, g_w2h);
        cudaFuncSetAttribute((const void*)moe_gemm<DDIM, IDIM, false>,
                             cudaFuncAttributeMaxDynamicSharedMemorySize, SMEM_BYTES);
        cudaFuncSetAttribute((const void*)moe_gemm<IDIM, DDIM, true>,
                             cudaFuncAttributeMaxDynamicSharedMemorySize, SMEM_BYTES);
    }

    int n4 = out_size / 4;                 // 1M float4 (out and x same size)
    int w4 = (NEXP * DDIM * IDIM) / 4;     // 4M float4 per weight tensor

    // 1: prep (zero out + convert x + dtype), 2: route, 3: w1 conversion
    prep_kernel<<<(n4 + 255) / 256, 256>>>((float4*)out, (const float4*)x, se32, n4);
    route_kernel<<<1, 256>>>(se32, rw);
    conv_half_kernel<<<(w4 + 255) / 256, 256>>>((const float4*)w1, (uint2*)p_w1h, w4);

    // 4: GEMM1 (z==8 blocks convert w2 concurrently)
    dim3 g1(IDIM / 128, NASN / 128, NEXP + 1);   // (16, 64, 9)
    moe_gemm<DDIM, IDIM, false><<<g1, 256, SMEM_BYTES>>>(out, (const float4*)w2, (uint2*)p_w2h);

    // 5: GEMM2
    dim3 g2(DDIM / 128, NASN / 128, NEXP);       // (8, 64, 8)
    moe_gemm<IDIM, DDIM, true><<<g2, 256, SMEM_BYTES>>>(out, nullptr, nullptr);
}